// round 6
// baseline (speedup 1.0000x reference)
#include <cuda_runtime.h>

// rate_RNN_mante: T=1000, B=64, I=4, H=1024, O=2, P=16
// Low-rank recurrence: r @ Wr^T = (r @ pout) @ (l*pin)^T
// One persistent CTA per batch element; mem state in registers.
// R6: packed fma.rn.f32x2 on phase-1 accumulate and phase-3 feedback;
//     z broadcast stored duplicated in smem as (z,z) pairs.

#define T_STEPS 1000
#define BATCH   64
#define I_DIM   4
#define H_DIM   1024
#define O_DIM   2
#define P_DIM   16
#define HPT     4                 // h-rows per thread
#define NTHREADS 256              // H_DIM / HPT
#define NWARPS  (NTHREADS / 32)
#define NRED    18                // 16 z-values + 2 y-values
#define NRED2   9                 // packed pairs
#define PROW    20                // pbuf row stride (floats), conflict-free columns

typedef unsigned long long u64;

__device__ __forceinline__ float fast_tanh(float x) {
    float r;
    asm("tanh.approx.f32 %0, %1;" : "=f"(r) : "f"(x));
    return r;
}
__device__ __forceinline__ float shfl_xor_f(float v, int off) {
    return __shfl_xor_sync(0xffffffffu, v, off);
}
__device__ __forceinline__ u64 pk2(float lo, float hi) {
    u64 r; asm("mov.b64 %0, {%1, %2};" : "=l"(r) : "f"(lo), "f"(hi)); return r;
}
__device__ __forceinline__ void upk2(u64 v, float& lo, float& hi) {
    asm("mov.b64 {%0, %1}, %2;" : "=f"(lo), "=f"(hi) : "l"(v));
}
__device__ __forceinline__ u64 fma2(u64 a, u64 b, u64 c) {
    u64 d; asm("fma.rn.f32x2 %0, %1, %2, %3;" : "=l"(d) : "l"(a), "l"(b), "l"(c)); return d;
}
__device__ __forceinline__ u64 add2(u64 a, u64 b) {
    u64 d; asm("add.rn.f32x2 %0, %1, %2;" : "=l"(d) : "l"(a), "l"(b)); return d;
}
__device__ __forceinline__ u64 mul2(u64 a, u64 b) {
    u64 d; asm("mul.rn.f32x2 %0, %1, %2;" : "=l"(d) : "l"(a), "l"(b)); return d;
}

__global__ __launch_bounds__(NTHREADS, 1)
void rate_rnn_kernel(const float* __restrict__ x,     // (T,B,I,1)
                     const float* __restrict__ Win,   // (H,I)
                     const float* __restrict__ Wout,  // (O,H)
                     const float* __restrict__ pin,   // (H,P)
                     const float* __restrict__ pout,  // (H,P)
                     const float* __restrict__ l,     // (P,)
                     float* __restrict__ y)           // (T,B,O,1)
{
    const int b    = blockIdx.x;
    const int tid  = threadIdx.x;
    const int lane = tid & 31;
    const int warp = tid >> 5;

    __shared__ __align__(16) float pbuf[NWARPS][PROW];   // per-warp reduced values
    __shared__ __align__(16) float zbuf2[2 * P_DIM];     // z duplicated as (z,z) pairs

    const float lm = 0.95122942450071400910f;  // exp(-DT/TAUM) = exp(-0.05)
    const float om = 1.0f - lm;
    const u64 lm2  = pk2(lm, lm);

    // split-butterfly lane roles
    const bool hi16 = (lane & 16) != 0;
    const bool hi8  = (lane & 8)  != 0;
    const bool hi4  = (lane & 4)  != 0;
    const bool hi2  = (lane & 2)  != 0;
    const bool wz   = (lane & 1)  == 0;           // z writer lanes
    const int  zj   = (lane >> 1) & 15;           // z index this lane-pair owns
    const bool wy   = (lane & 15) == 0;           // y writer lanes (0 and 16)
    const int  yj   = 16 + (lane >> 4);           // y index

    // ---- setup: load scalar, then pack ----
    float lvec[P_DIM];
    #pragma unroll
    for (int p = 0; p < P_DIM; p++) lvec[p] = l[p];

    float msc[HPT][NRED];      // scalar staging: [pout(16) | Wout^T(2)]
    float wsc[HPT][I_DIM];     // om * Win
    float lsc[HPT][P_DIM];     // om * l * pin
    #pragma unroll
    for (int k = 0; k < HPT; k++) {
        const int h = tid + k * NTHREADS;
        #pragma unroll
        for (int i = 0; i < I_DIM; i++) wsc[k][i] = om * Win[h * I_DIM + i];
        #pragma unroll
        for (int p = 0; p < P_DIM; p++) {
            msc[k][p] = pout[h * P_DIM + p];
            lsc[k][p] = om * lvec[p] * pin[h * P_DIM + p];
        }
        msc[k][16] = Wout[h];
        msc[k][17] = Wout[H_DIM + h];
    }

    u64 m2[HPT][NRED2];        // packed along j
    #pragma unroll
    for (int k = 0; k < HPT; k++)
        #pragma unroll
        for (int j = 0; j < NRED2; j++)
            m2[k][j] = pk2(msc[k][2 * j], msc[k][2 * j + 1]);

    u64 win2[2][I_DIM];        // packed along k-pairs (k=2c, 2c+1)
    u64 lp2[2][P_DIM];
    #pragma unroll
    for (int c = 0; c < 2; c++) {
        #pragma unroll
        for (int i = 0; i < I_DIM; i++) win2[c][i] = pk2(wsc[2 * c][i], wsc[2 * c + 1][i]);
        #pragma unroll
        for (int p = 0; p < P_DIM; p++) lp2[c][p]  = pk2(lsc[2 * c][p], lsc[2 * c + 1][p]);
    }

    u64 mem2[2];               // (mem_k0, mem_k1), (mem_k2, mem_k3)
    mem2[0] = 0ull;            // bit pattern 0 == (0.f, 0.f)
    mem2[1] = 0ull;

    const float4* xp = reinterpret_cast<const float4*>(x) + b;
    float4 xc = __ldg(xp);   // t = 0
    float4 xn = xc;

    // Iteration t: r_t = tanh(mem_t); y[t-1] = Wout.r_t; advance mem (t < T).
    for (int t = 0; t <= T_STEPS; t++) {
        {   // clamped prefetch of next x
            int tn = t + 1; if (tn > T_STEPS - 1) tn = T_STEPS - 1;
            xn = __ldg(xp + tn * BATCH);
        }

        // ---- phase 1: tanh + packed accumulation ----
        float mk[HPT];
        upk2(mem2[0], mk[0], mk[1]);
        upk2(mem2[1], mk[2], mk[3]);

        u64 part2[NRED2];
        #pragma unroll
        for (int j = 0; j < NRED2; j++) part2[j] = 0ull;

        #pragma unroll
        for (int k = 0; k < HPT; k++) {
            const float r = fast_tanh(mk[k]);
            const u64 rr = pk2(r, r);
            #pragma unroll
            for (int j = 0; j < NRED2; j++)
                part2[j] = fma2(rr, m2[k][j], part2[j]);
        }

        float part[NRED];
        #pragma unroll
        for (int j = 0; j < NRED2; j++) upk2(part2[j], part[2 * j], part[2 * j + 1]);

        // ---- split-butterfly: 16 z values, halving live set each round ----
        float v8[8];
        #pragma unroll
        for (int i = 0; i < 8; i++) {
            float send = hi16 ? part[i] : part[i + 8];
            float keep = hi16 ? part[i + 8] : part[i];
            v8[i] = keep + shfl_xor_f(send, 16);
        }
        float v4[4];
        #pragma unroll
        for (int i = 0; i < 4; i++) {
            float send = hi8 ? v8[i] : v8[i + 4];
            float keep = hi8 ? v8[i + 4] : v8[i];
            v4[i] = keep + shfl_xor_f(send, 8);
        }
        float v2[2];
        #pragma unroll
        for (int i = 0; i < 2; i++) {
            float send = hi4 ? v4[i] : v4[i + 2];
            float keep = hi4 ? v4[i + 2] : v4[i];
            v2[i] = keep + shfl_xor_f(send, 4);
        }
        float v1;
        {
            float send = hi2 ? v2[0] : v2[1];
            float keep = hi2 ? v2[1] : v2[0];
            v1 = keep + shfl_xor_f(send, 2);
        }
        v1 += shfl_xor_f(v1, 1);   // lane pair holds z[zj]

        // ---- y values: split once, then 4 naive rounds ----
        float wv;
        {
            float send = hi16 ? part[16] : part[17];
            float keep = hi16 ? part[17] : part[16];
            wv = keep + shfl_xor_f(send, 16);
        }
        wv += shfl_xor_f(wv, 8);
        wv += shfl_xor_f(wv, 4);
        wv += shfl_xor_f(wv, 2);
        wv += shfl_xor_f(wv, 1);

        if (wz) pbuf[warp][zj] = v1;
        if (wy) pbuf[warp][yj] = wv;
        __syncthreads();

        // ---- phase 2: cross-warp reduce; z (duplicated) -> smem, y -> global ----
        if (tid < NRED) {
            float s = pbuf[0][tid];
            #pragma unroll
            for (int w = 1; w < NWARPS; w++) s += pbuf[w][tid];
            if (tid < P_DIM) {
                reinterpret_cast<u64*>(zbuf2)[tid] = pk2(s, s);   // store (z,z)
            } else if (t > 0) {
                y[((t - 1) * BATCH + b) * O_DIM + (tid - P_DIM)] = s;
            }
        }
        __syncthreads();

        if (t == T_STEPS) break;

        // ---- phase 3: packed feedback + leaky integration ----
        u64 zz[P_DIM];
        {
            const ulonglong2* zv = reinterpret_cast<const ulonglong2*>(zbuf2);
            #pragma unroll
            for (int q = 0; q < 8; q++) {
                ulonglong2 v = zv[q];
                zz[2 * q]     = v.x;
                zz[2 * q + 1] = v.y;
            }
        }
        u64 xx[I_DIM];
        xx[0] = pk2(xc.x, xc.x);
        xx[1] = pk2(xc.y, xc.y);
        xx[2] = pk2(xc.z, xc.z);
        xx[3] = pk2(xc.w, xc.w);

        #pragma unroll
        for (int c = 0; c < 2; c++) {
            u64 a0 = mul2(lm2, mem2[c]);
            #pragma unroll
            for (int i = 0; i < I_DIM; i++)
                a0 = fma2(win2[c][i], xx[i], a0);

            u64 a1 = mul2(zz[0], lp2[c][0]);
            #pragma unroll
            for (int p = 1; p < 8; p++)
                a1 = fma2(zz[p], lp2[c][p], a1);

            u64 a2 = mul2(zz[8], lp2[c][8]);
            #pragma unroll
            for (int p = 9; p < 16; p++)
                a2 = fma2(zz[p], lp2[c][p], a2);

            mem2[c] = add2(a0, add2(a1, a2));
        }
        xc = xn;
    }
}

extern "C" void kernel_launch(void* const* d_in, const int* in_sizes, int n_in,
                              void* d_out, int out_size)
{
    const float* x    = (const float*)d_in[0];
    const float* Win  = (const float*)d_in[1];
    const float* Wout = (const float*)d_in[2];
    const float* pin  = (const float*)d_in[3];
    const float* pout = (const float*)d_in[4];
    const float* l    = (const float*)d_in[5];
    float* y = (float*)d_out;

    rate_rnn_kernel<<<BATCH, NTHREADS>>>(x, Win, Wout, pin, pout, l, y);
}

// round 7
// speedup vs baseline: 1.0172x; 1.0172x over previous
#include <cuda_runtime.h>

// rate_RNN_mante: T=1000, B=64, I=4, H=1024, O=2, P=16
// Low-rank recurrence: r @ Wr^T = (r @ pout) @ (l*pin)^T
// One persistent CTA per batch element; mem state in registers.
// R7: single __syncthreads per step (double-buffered partials + redundant
//     per-warp cross-warp reduce + shfl.idx z broadcast), 4-round butterfly,
//     z-independent drive hoisted before the barrier. Scalar FMA (f32x2 reverted).

#define T_STEPS 1000
#define BATCH   64
#define I_DIM   4
#define H_DIM   1024
#define O_DIM   2
#define P_DIM   16
#define HPT     4                 // h-rows per thread
#define NTHREADS 256              // H_DIM / HPT
#define NWARPS  (NTHREADS / 32)
#define NRED    18                // 16 z-values + 2 y-values
#define PROW    34                // 32 z-partial cols + 2 y cols

__device__ __forceinline__ float fast_tanh(float x) {
    float r;
    asm("tanh.approx.f32 %0, %1;" : "=f"(r) : "f"(x));
    return r;
}
__device__ __forceinline__ float shfl_xor_f(float v, int off) {
    return __shfl_xor_sync(0xffffffffu, v, off);
}

__global__ __launch_bounds__(NTHREADS, 1)
void rate_rnn_kernel(const float* __restrict__ x,     // (T,B,I,1)
                     const float* __restrict__ Win,   // (H,I)
                     const float* __restrict__ Wout,  // (O,H)
                     const float* __restrict__ pin,   // (H,P)
                     const float* __restrict__ pout,  // (H,P)
                     const float* __restrict__ l,     // (P,)
                     float* __restrict__ y)           // (T,B,O,1)
{
    const int b    = blockIdx.x;
    const int tid  = threadIdx.x;
    const int lane = tid & 31;
    const int warp = tid >> 5;

    // double-buffered per-warp partials: [parity][warp][32 z-partials | 2 y]
    __shared__ __align__(16) float pbuf[2][NWARPS][PROW];

    const float lm = 0.95122942450071400910f;  // exp(-DT/TAUM) = exp(-0.05)
    const float om = 1.0f - lm;

    // butterfly lane roles
    const bool hi16 = (lane & 16) != 0;
    const bool hi8  = (lane & 8)  != 0;
    const bool hi4  = (lane & 4)  != 0;
    const bool hi2  = (lane & 2)  != 0;
    const bool wy   = (lane & 15) == 0;           // y writer lanes (0 and 16)
    const int  ycol = 32 + (lane >> 4);           // y column in pbuf row

    float lvec[P_DIM];
    #pragma unroll
    for (int p = 0; p < P_DIM; p++) lvec[p] = l[p];

    float mem[HPT];
    float win[HPT][I_DIM];     // om * Win
    float m[HPT][NRED];        // [pout(16) | Wout^T(2)]
    float lp[HPT][P_DIM];      // om * l * pin

    #pragma unroll
    for (int k = 0; k < HPT; k++) {
        const int h = tid + k * NTHREADS;
        mem[k] = 0.0f;
        #pragma unroll
        for (int i = 0; i < I_DIM; i++) win[k][i] = om * Win[h * I_DIM + i];
        #pragma unroll
        for (int p = 0; p < P_DIM; p++) {
            m[k][p]  = pout[h * P_DIM + p];
            lp[k][p] = om * lvec[p] * pin[h * P_DIM + p];
        }
        m[k][16] = Wout[h];           // Wout[0][h]
        m[k][17] = Wout[H_DIM + h];   // Wout[1][h]
    }

    const float4* xp = reinterpret_cast<const float4*>(x) + b;
    float4 xc = __ldg(xp);   // t = 0
    float4 xn = xc;

    // Iteration t: r_t = tanh(mem_t); y[t-1] = Wout.r_t; advance mem (t < T).
    for (int t = 0; t <= T_STEPS; t++) {
        {   // clamped prefetch of next x
            int tn = t + 1; if (tn > T_STEPS - 1) tn = T_STEPS - 1;
            xn = __ldg(xp + tn * BATCH);
        }
        float (*pb)[PROW] = pbuf[t & 1];

        // ---- phase 1: tanh + local accumulation ----
        float part[NRED];
        #pragma unroll
        for (int j = 0; j < NRED; j++) part[j] = 0.0f;

        #pragma unroll
        for (int k = 0; k < HPT; k++) {
            const float r = fast_tanh(mem[k]);
            #pragma unroll
            for (int j = 0; j < NRED; j++)
                part[j] = fmaf(r, m[k][j], part[j]);
        }

        // ---- z-independent drive, hoisted off the post-barrier path ----
        float a0r[HPT];
        #pragma unroll
        for (int k = 0; k < HPT; k++) {
            float a = lm * mem[k];
            a = fmaf(win[k][0], xc.x, a);
            a = fmaf(win[k][1], xc.y, a);
            a = fmaf(win[k][2], xc.z, a);
            a = fmaf(win[k][3], xc.w, a);
            a0r[k] = a;
        }

        // ---- split-butterfly: rounds 16/8/4/2 (no final xor-1) ----
        float v8[8];
        #pragma unroll
        for (int i = 0; i < 8; i++) {
            float send = hi16 ? part[i] : part[i + 8];
            float keep = hi16 ? part[i + 8] : part[i];
            v8[i] = keep + shfl_xor_f(send, 16);
        }
        float v4[4];
        #pragma unroll
        for (int i = 0; i < 4; i++) {
            float send = hi8 ? v8[i] : v8[i + 4];
            float keep = hi8 ? v8[i + 4] : v8[i];
            v4[i] = keep + shfl_xor_f(send, 8);
        }
        float v2[2];
        #pragma unroll
        for (int i = 0; i < 2; i++) {
            float send = hi4 ? v4[i] : v4[i + 2];
            float keep = hi4 ? v4[i + 2] : v4[i];
            v2[i] = keep + shfl_xor_f(send, 4);
        }
        float v1;
        {
            float send = hi2 ? v2[0] : v2[1];
            float keep = hi2 ? v2[1] : v2[0];
            v1 = keep + shfl_xor_f(send, 2);
        }
        // lane L holds one of two partials of z[(L>>1)&15]

        // ---- y values: split once, then 4 naive rounds (full warp sum) ----
        float wv;
        {
            float send = hi16 ? part[16] : part[17];
            float keep = hi16 ? part[17] : part[16];
            wv = keep + shfl_xor_f(send, 16);
        }
        wv += shfl_xor_f(wv, 8);
        wv += shfl_xor_f(wv, 4);
        wv += shfl_xor_f(wv, 2);
        wv += shfl_xor_f(wv, 1);

        pb[warp][lane] = v1;          // full-warp coalesced, no predicate
        if (wy) pb[warp][ycol] = wv;  // lanes 0 (y0) and 16 (y1)
        __syncthreads();              // the ONLY barrier per step

        // ---- redundant per-warp cross-warp reduce (lanes 0..16) ----
        float sx = 0.0f, sy = 0.0f;
        if (lane < 17) {
            const int c = 2 * lane;   // lane 16 -> cols 32,33 = (y0,y1)
            float2 q0 = *reinterpret_cast<const float2*>(&pb[0][c]);
            float2 q1 = *reinterpret_cast<const float2*>(&pb[1][c]);
            float2 q2 = *reinterpret_cast<const float2*>(&pb[2][c]);
            float2 q3 = *reinterpret_cast<const float2*>(&pb[3][c]);
            float2 q4 = *reinterpret_cast<const float2*>(&pb[4][c]);
            float2 q5 = *reinterpret_cast<const float2*>(&pb[5][c]);
            float2 q6 = *reinterpret_cast<const float2*>(&pb[6][c]);
            float2 q7 = *reinterpret_cast<const float2*>(&pb[7][c]);
            float ax = (q0.x + q1.x) + (q2.x + q3.x);
            float bx = (q4.x + q5.x) + (q6.x + q7.x);
            float ay = (q0.y + q1.y) + (q2.y + q3.y);
            float by = (q4.y + q5.y) + (q6.y + q7.y);
            sx = ax + bx;
            sy = ay + by;
        }
        const float zval = sx + sy;   // lanes 0..15: z[lane]; others unused

        // y store: lane 16 of warp 0 holds (y_o0, y_o1) in (sx, sy)
        if (warp == 0 && lane == 16 && t > 0) {
            *reinterpret_cast<float2*>(&y[((t - 1) * BATCH + b) * O_DIM]) =
                make_float2(sx, sy);
        }

        if (t == T_STEPS) break;

        // ---- broadcast z within warp ----
        float zp[P_DIM];
        #pragma unroll
        for (int p = 0; p < P_DIM; p++)
            zp[p] = __shfl_sync(0xffffffffu, zval, p);

        // ---- phase 3: z feedback (two 8-deep trees) + hoisted drive ----
        #pragma unroll
        for (int k = 0; k < HPT; k++) {
            float a1 = zp[0] * lp[k][0];
            a1 = fmaf(zp[1], lp[k][1], a1);
            a1 = fmaf(zp[2], lp[k][2], a1);
            a1 = fmaf(zp[3], lp[k][3], a1);
            a1 = fmaf(zp[4], lp[k][4], a1);
            a1 = fmaf(zp[5], lp[k][5], a1);
            a1 = fmaf(zp[6], lp[k][6], a1);
            a1 = fmaf(zp[7], lp[k][7], a1);

            float a2 = zp[8] * lp[k][8];
            a2 = fmaf(zp[9],  lp[k][9],  a2);
            a2 = fmaf(zp[10], lp[k][10], a2);
            a2 = fmaf(zp[11], lp[k][11], a2);
            a2 = fmaf(zp[12], lp[k][12], a2);
            a2 = fmaf(zp[13], lp[k][13], a2);
            a2 = fmaf(zp[14], lp[k][14], a2);
            a2 = fmaf(zp[15], lp[k][15], a2);

            mem[k] = a0r[k] + (a1 + a2);
        }
        xc = xn;
    }
}

extern "C" void kernel_launch(void* const* d_in, const int* in_sizes, int n_in,
                              void* d_out, int out_size)
{
    const float* x    = (const float*)d_in[0];
    const float* Win  = (const float*)d_in[1];
    const float* Wout = (const float*)d_in[2];
    const float* pin  = (const float*)d_in[3];
    const float* pout = (const float*)d_in[4];
    const float* l    = (const float*)d_in[5];
    float* y = (float*)d_out;

    rate_rnn_kernel<<<BATCH, NTHREADS>>>(x, Win, Wout, pin, pout, l, y);
}

// round 9
// speedup vs baseline: 1.0329x; 1.0154x over previous
#include <cuda_runtime.h>

// rate_RNN_mante: T=1000, B=64, I=4, H=1024, O=2, P=16
// Low-rank recurrence: r @ Wr^T = (r @ pout) @ (l*pin)^T
// One persistent CTA per batch element; mem state in registers.
// R9 = R8 resubmission (infra failure, kernel never ran):
// R7 structure (single barrier, double-buffered partials, redundant
// per-warp cross-warp reduce, hoisted drive) + R6 f32x2 packing.

#define T_STEPS 1000
#define BATCH   64
#define I_DIM   4
#define H_DIM   1024
#define O_DIM   2
#define P_DIM   16
#define HPT     4                 // h-rows per thread
#define NTHREADS 256              // H_DIM / HPT
#define NWARPS  (NTHREADS / 32)
#define NRED    18                // 16 z-values + 2 y-values
#define NRED2   9
#define PROW    34                // 32 z-partial cols + 2 y cols (even -> 8B aligned rows)

typedef unsigned long long u64;

__device__ __forceinline__ float fast_tanh(float x) {
    float r;
    asm("tanh.approx.f32 %0, %1;" : "=f"(r) : "f"(x));
    return r;
}
__device__ __forceinline__ float shfl_xor_f(float v, int off) {
    return __shfl_xor_sync(0xffffffffu, v, off);
}
__device__ __forceinline__ u64 pk2(float lo, float hi) {
    u64 r; asm("mov.b64 %0, {%1, %2};" : "=l"(r) : "f"(lo), "f"(hi)); return r;
}
__device__ __forceinline__ void upk2(u64 v, float& lo, float& hi) {
    asm("mov.b64 {%0, %1}, %2;" : "=f"(lo), "=f"(hi) : "l"(v));
}
__device__ __forceinline__ u64 fma2(u64 a, u64 b, u64 c) {
    u64 d; asm("fma.rn.f32x2 %0, %1, %2, %3;" : "=l"(d) : "l"(a), "l"(b), "l"(c)); return d;
}
__device__ __forceinline__ u64 add2(u64 a, u64 b) {
    u64 d; asm("add.rn.f32x2 %0, %1, %2;" : "=l"(d) : "l"(a), "l"(b)); return d;
}
__device__ __forceinline__ u64 mul2(u64 a, u64 b) {
    u64 d; asm("mul.rn.f32x2 %0, %1, %2;" : "=l"(d) : "l"(a), "l"(b)); return d;
}

__global__ __launch_bounds__(NTHREADS, 1)
void rate_rnn_kernel(const float* __restrict__ x,     // (T,B,I,1)
                     const float* __restrict__ Win,   // (H,I)
                     const float* __restrict__ Wout,  // (O,H)
                     const float* __restrict__ pin,   // (H,P)
                     const float* __restrict__ pout,  // (H,P)
                     const float* __restrict__ l,     // (P,)
                     float* __restrict__ y)           // (T,B,O,1)
{
    const int b    = blockIdx.x;
    const int tid  = threadIdx.x;
    const int lane = tid & 31;
    const int warp = tid >> 5;

    // double-buffered per-warp partials: [parity][warp][32 z-partials | 2 y]
    __shared__ __align__(16) float pbuf[2][NWARPS][PROW];

    const float lm = 0.95122942450071400910f;  // exp(-DT/TAUM) = exp(-0.05)
    const float om = 1.0f - lm;
    const u64 lm2  = pk2(lm, lm);

    // butterfly lane roles
    const bool hi16 = (lane & 16) != 0;
    const bool hi8  = (lane & 8)  != 0;
    const bool hi4  = (lane & 4)  != 0;
    const bool hi2  = (lane & 2)  != 0;
    const bool wy   = (lane & 15) == 0;           // y writer lanes (0 and 16)
    const int  ycol = 32 + (lane >> 4);           // y column in pbuf row

    // ---- setup: scalar staging, then pack ----
    float lvec[P_DIM];
    #pragma unroll
    for (int p = 0; p < P_DIM; p++) lvec[p] = l[p];

    float msc[HPT][NRED];      // [pout(16) | Wout^T(2)]
    float wsc[HPT][I_DIM];     // om * Win
    float lsc[HPT][P_DIM];     // om * l * pin
    #pragma unroll
    for (int k = 0; k < HPT; k++) {
        const int h = tid + k * NTHREADS;
        #pragma unroll
        for (int i = 0; i < I_DIM; i++) wsc[k][i] = om * Win[h * I_DIM + i];
        #pragma unroll
        for (int p = 0; p < P_DIM; p++) {
            msc[k][p] = pout[h * P_DIM + p];
            lsc[k][p] = om * lvec[p] * pin[h * P_DIM + p];
        }
        msc[k][16] = Wout[h];
        msc[k][17] = Wout[H_DIM + h];
    }

    u64 m2[HPT][NRED2];        // packed along j (phase 1)
    #pragma unroll
    for (int k = 0; k < HPT; k++)
        #pragma unroll
        for (int j = 0; j < NRED2; j++)
            m2[k][j] = pk2(msc[k][2 * j], msc[k][2 * j + 1]);

    u64 win2[2][I_DIM];        // packed along k-pairs (phase 3)
    u64 lp2[2][P_DIM];
    #pragma unroll
    for (int c = 0; c < 2; c++) {
        #pragma unroll
        for (int i = 0; i < I_DIM; i++) win2[c][i] = pk2(wsc[2 * c][i], wsc[2 * c + 1][i]);
        #pragma unroll
        for (int p = 0; p < P_DIM; p++) lp2[c][p]  = pk2(lsc[2 * c][p], lsc[2 * c + 1][p]);
    }

    u64 mem2[2] = {0ull, 0ull};   // (mem_k0,mem_k1), (mem_k2,mem_k3)

    const float4* xp = reinterpret_cast<const float4*>(x) + b;
    float4 xc = __ldg(xp);   // t = 0
    float4 xn = xc;

    // Iteration t: r_t = tanh(mem_t); y[t-1] = Wout.r_t; advance mem (t < T).
    for (int t = 0; t <= T_STEPS; t++) {
        {   // clamped prefetch of next x
            int tn = t + 1; if (tn > T_STEPS - 1) tn = T_STEPS - 1;
            xn = __ldg(xp + tn * BATCH);
        }
        float (*pb)[PROW] = pbuf[t & 1];

        // ---- phase 1: tanh + packed accumulation ----
        float mk[HPT];
        upk2(mem2[0], mk[0], mk[1]);
        upk2(mem2[1], mk[2], mk[3]);

        u64 part2[NRED2];
        #pragma unroll
        for (int j = 0; j < NRED2; j++) part2[j] = 0ull;

        #pragma unroll
        for (int k = 0; k < HPT; k++) {
            const float r = fast_tanh(mk[k]);
            const u64 rr = pk2(r, r);
            #pragma unroll
            for (int j = 0; j < NRED2; j++)
                part2[j] = fma2(rr, m2[k][j], part2[j]);
        }
        float part[NRED];
        #pragma unroll
        for (int j = 0; j < NRED2; j++) upk2(part2[j], part[2 * j], part[2 * j + 1]);

        // ---- z-independent drive, hoisted & packed ----
        u64 xx[I_DIM];
        xx[0] = pk2(xc.x, xc.x);
        xx[1] = pk2(xc.y, xc.y);
        xx[2] = pk2(xc.z, xc.z);
        xx[3] = pk2(xc.w, xc.w);
        u64 a0p[2];
        #pragma unroll
        for (int c = 0; c < 2; c++) {
            u64 a = mul2(lm2, mem2[c]);
            #pragma unroll
            for (int i = 0; i < I_DIM; i++)
                a = fma2(win2[c][i], xx[i], a);
            a0p[c] = a;
        }

        // ---- split-butterfly: rounds 16/8/4/2 (no final xor-1) ----
        float v8[8];
        #pragma unroll
        for (int i = 0; i < 8; i++) {
            float send = hi16 ? part[i] : part[i + 8];
            float keep = hi16 ? part[i + 8] : part[i];
            v8[i] = keep + shfl_xor_f(send, 16);
        }
        float v4[4];
        #pragma unroll
        for (int i = 0; i < 4; i++) {
            float send = hi8 ? v8[i] : v8[i + 4];
            float keep = hi8 ? v8[i + 4] : v8[i];
            v4[i] = keep + shfl_xor_f(send, 8);
        }
        float v2[2];
        #pragma unroll
        for (int i = 0; i < 2; i++) {
            float send = hi4 ? v4[i] : v4[i + 2];
            float keep = hi4 ? v4[i + 2] : v4[i];
            v2[i] = keep + shfl_xor_f(send, 4);
        }
        float v1;
        {
            float send = hi2 ? v2[0] : v2[1];
            float keep = hi2 ? v2[1] : v2[0];
            v1 = keep + shfl_xor_f(send, 2);
        }
        // lane L holds one of two partials of z[(L>>1)&15]

        // ---- y: split once, then 4 naive rounds ----
        float wv;
        {
            float send = hi16 ? part[16] : part[17];
            float keep = hi16 ? part[17] : part[16];
            wv = keep + shfl_xor_f(send, 16);
        }
        wv += shfl_xor_f(wv, 8);
        wv += shfl_xor_f(wv, 4);
        wv += shfl_xor_f(wv, 2);
        wv += shfl_xor_f(wv, 1);

        pb[warp][lane] = v1;          // coalesced, no predicate
        if (wy) pb[warp][ycol] = wv;  // lanes 0 (y0) and 16 (y1)
        __syncthreads();              // the ONLY barrier per step

        // ---- redundant per-warp cross-warp reduce (lanes 0..16), packed ----
        float sx = 0.0f, sy = 0.0f;
        if (lane < 17) {
            const int c = 2 * lane;   // lane 16 -> cols 32,33 = (y0,y1)
            u64 q0 = *reinterpret_cast<const u64*>(&pb[0][c]);
            u64 q1 = *reinterpret_cast<const u64*>(&pb[1][c]);
            u64 q2 = *reinterpret_cast<const u64*>(&pb[2][c]);
            u64 q3 = *reinterpret_cast<const u64*>(&pb[3][c]);
            u64 q4 = *reinterpret_cast<const u64*>(&pb[4][c]);
            u64 q5 = *reinterpret_cast<const u64*>(&pb[5][c]);
            u64 q6 = *reinterpret_cast<const u64*>(&pb[6][c]);
            u64 q7 = *reinterpret_cast<const u64*>(&pb[7][c]);
            u64 s = add2(add2(add2(q0, q1), add2(q2, q3)),
                         add2(add2(q4, q5), add2(q6, q7)));
            upk2(s, sx, sy);
        }
        const float zval = sx + sy;   // lanes 0..15: z[lane]

        // y store: lane 16 of warp 0 holds (y_o0, y_o1) in (sx, sy)
        if (warp == 0 && lane == 16 && t > 0) {
            *reinterpret_cast<float2*>(&y[((t - 1) * BATCH + b) * O_DIM]) =
                make_float2(sx, sy);
        }

        if (t == T_STEPS) break;

        // ---- broadcast z within warp, pack as (z,z) ----
        u64 zz[P_DIM];
        #pragma unroll
        for (int p = 0; p < P_DIM; p++) {
            float zp = __shfl_sync(0xffffffffu, zval, p);
            zz[p] = pk2(zp, zp);
        }

        // ---- phase 3: packed z feedback + hoisted drive ----
        #pragma unroll
        for (int c = 0; c < 2; c++) {
            u64 a1 = mul2(zz[0], lp2[c][0]);
            #pragma unroll
            for (int p = 1; p < 8; p++)
                a1 = fma2(zz[p], lp2[c][p], a1);

            u64 a2 = mul2(zz[8], lp2[c][8]);
            #pragma unroll
            for (int p = 9; p < 16; p++)
                a2 = fma2(zz[p], lp2[c][p], a2);

            mem2[c] = add2(a0p[c], add2(a1, a2));
        }
        xc = xn;
    }
}

extern "C" void kernel_launch(void* const* d_in, const int* in_sizes, int n_in,
                              void* d_out, int out_size)
{
    const float* x    = (const float*)d_in[0];
    const float* Win  = (const float*)d_in[1];
    const float* Wout = (const float*)d_in[2];
    const float* pin  = (const float*)d_in[3];
    const float* pout = (const float*)d_in[4];
    const float* l    = (const float*)d_in[5];
    float* y = (float*)d_out;

    rate_rnn_kernel<<<BATCH, NTHREADS>>>(x, Win, Wout, pin, pout, l, y);
}